// round 1
// baseline (speedup 1.0000x reference)
#include <cuda_runtime.h>
#include <math.h>

#define B_ 4
#define N_ 2048
#define M_ 2048
#define C_ 1024
#define H_ 16
#define D_ 64
#define SCALE_ 0.125f

// Scratch (allocation-free rule: __device__ globals)
__device__ float g_q[(size_t)B_ * H_ * N_ * D_];   // (B,H,N,D)
__device__ float g_k[(size_t)B_ * H_ * M_ * D_];   // (B,H,M,D)
__device__ float g_v[(size_t)B_ * H_ * M_ * D_];   // (B,H,M,D)
__device__ float g_x[(size_t)B_ * N_ * C_];        // (B,N,C) attention output

// ---------------------------------------------------------------------------
// 128x128 tile fp32 GEMM (NT form): out[r][c] = sum_k X[r*1024+k] * W[c*1024+k]
// 256 threads, 8x8 per-thread micro-tile, BK=8, register prefetch of gmem.
// ---------------------------------------------------------------------------
__device__ __forceinline__ void sgemm128(const float* __restrict__ X,
                                         const float* __restrict__ W,
                                         int row0, int col0, float acc[8][8]) {
    __shared__ float As[8][132];   // As[k][m], padded to kill transpose-store conflicts
    __shared__ float Bs[8][132];   // Bs[k][n]
    const int tid = threadIdx.x;
    const int lr  = tid >> 1;          // 0..127 row/col within tile
    const int lk  = (tid & 1) << 2;    // 0 or 4
    const int ty  = tid >> 4;          // 0..15
    const int tx  = tid & 15;          // 0..15

    const float* Ap = X + (size_t)(row0 + lr) * C_ + lk;
    const float* Wp = W + (size_t)(col0 + lr) * C_ + lk;

    float4 av = *(const float4*)Ap;
    float4 bv = *(const float4*)Wp;

    for (int kt = 0; kt < C_ / 8; ++kt) {
        As[lk + 0][lr] = av.x; As[lk + 1][lr] = av.y;
        As[lk + 2][lr] = av.z; As[lk + 3][lr] = av.w;
        Bs[lk + 0][lr] = bv.x; Bs[lk + 1][lr] = bv.y;
        Bs[lk + 2][lr] = bv.z; Bs[lk + 3][lr] = bv.w;
        __syncthreads();
        if (kt + 1 < C_ / 8) {                 // prefetch next k-slab into regs
            av = *(const float4*)(Ap + (kt + 1) * 8);
            bv = *(const float4*)(Wp + (kt + 1) * 8);
        }
        #pragma unroll
        for (int k = 0; k < 8; ++k) {
            float4 a0 = *(const float4*)&As[k][ty * 8];
            float4 a1 = *(const float4*)&As[k][ty * 8 + 4];
            float4 b0 = *(const float4*)&Bs[k][tx * 8];
            float4 b1 = *(const float4*)&Bs[k][tx * 8 + 4];
            float a[8] = {a0.x, a0.y, a0.z, a0.w, a1.x, a1.y, a1.z, a1.w};
            float b[8] = {b0.x, b0.y, b0.z, b0.w, b1.x, b1.y, b1.z, b1.w};
            #pragma unroll
            for (int i = 0; i < 8; ++i)
                #pragma unroll
                for (int j = 0; j < 8; ++j)
                    acc[i][j] = fmaf(a[i], b[j], acc[i][j]);
        }
        __syncthreads();
    }
}

// ---------------------------------------------------------------------------
// QKV projections fused in one launch. z = 0/1/2 -> q/k/v.
// Output written directly in (B,H,S,D) layout for the attention kernel.
// ---------------------------------------------------------------------------
__global__ void __launch_bounds__(256) proj_qkv_kernel(
    const float* __restrict__ q_in, const float* __restrict__ k_in,
    const float* __restrict__ v_in, const float* __restrict__ Wq,
    const float* __restrict__ Wk, const float* __restrict__ Wv) {
    const float* X; const float* W; float* O;
    if (blockIdx.z == 0)      { X = q_in; W = Wq; O = g_q; }
    else if (blockIdx.z == 1) { X = k_in; W = Wk; O = g_k; }
    else                      { X = v_in; W = Wv; O = g_v; }

    const int row0 = blockIdx.y * 128;
    const int col0 = blockIdx.x * 128;

    float acc[8][8];
    #pragma unroll
    for (int i = 0; i < 8; ++i)
        #pragma unroll
        for (int j = 0; j < 8; ++j) acc[i][j] = 0.f;

    sgemm128(X, W, row0, col0, acc);

    const int ty = threadIdx.x >> 4, tx = threadIdx.x & 15;
    const int c0 = col0 + tx * 8;
    const int h  = c0 >> 6;          // 8-wide col chunk never crosses a head
    const int d0 = c0 & 63;
    #pragma unroll
    for (int i = 0; i < 8; ++i) {
        int r = row0 + ty * 8 + i;
        int b = r >> 11, s = r & 2047;
        float* op = O + (((size_t)(b * H_ + h) * N_ + s) * D_ + d0);
        *(float4*)op       = make_float4(acc[i][0], acc[i][1], acc[i][2], acc[i][3]);
        *(float4*)(op + 4) = make_float4(acc[i][4], acc[i][5], acc[i][6], acc[i][7]);
    }
}

// ---------------------------------------------------------------------------
// Output projection + bias -> d_out (B,N,C)
// ---------------------------------------------------------------------------
__global__ void __launch_bounds__(256) proj_out_kernel(
    const float* __restrict__ Wp, const float* __restrict__ bp,
    float* __restrict__ out) {
    const int row0 = blockIdx.y * 128;
    const int col0 = blockIdx.x * 128;

    float acc[8][8];
    #pragma unroll
    for (int i = 0; i < 8; ++i)
        #pragma unroll
        for (int j = 0; j < 8; ++j) acc[i][j] = 0.f;

    sgemm128(g_x, Wp, row0, col0, acc);

    const int ty = threadIdx.x >> 4, tx = threadIdx.x & 15;
    const int c0 = col0 + tx * 8;
    float bias[8];
    #pragma unroll
    for (int j = 0; j < 8; ++j) bias[j] = bp[c0 + j];
    #pragma unroll
    for (int i = 0; i < 8; ++i) {
        int r = row0 + ty * 8 + i;
        float* op = out + (size_t)r * C_ + c0;
        *(float4*)op       = make_float4(acc[i][0] + bias[0], acc[i][1] + bias[1],
                                         acc[i][2] + bias[2], acc[i][3] + bias[3]);
        *(float4*)(op + 4) = make_float4(acc[i][4] + bias[4], acc[i][5] + bias[5],
                                         acc[i][6] + bias[6], acc[i][7] + bias[7]);
    }
}

// ---------------------------------------------------------------------------
// Flash attention, fp32 SIMT.
// Block: 64 query rows of one (b,h). 256 threads = 16x16, 4x4 micro-tile.
// Smem (static, exactly 48KB):
//   Qt  : Q^T, swizzled, pre-scaled by SCALE     (element (d,n) of Q[n][d])
//   KtP : K^T swizzled for S;  reused as P^T for PV
//   Vs  : V natural [m][d]
// XOR swizzle keeps every fragment access a conflict-free/broadcast LDS.128.
// ---------------------------------------------------------------------------
#define SWZ(r, cg) ((((r)) << 6) + ((((cg) ^ ((r) & 15))) << 2))

__global__ void __launch_bounds__(256) flash_kernel() {
    __shared__ float Qt[64 * 64];
    __shared__ float KtP[64 * 64];
    __shared__ float Vs[64 * 64];

    const int tid = threadIdx.x;
    const int ty = tid >> 4;        // 0..15 (row group)
    const int tx = tid & 15;        // 0..15 (col group)
    const int bh = blockIdx.y;      // b*16 + h
    const int n0 = blockIdx.x * 64;

    const float* qb = g_q + (size_t)bh * N_ * D_;
    const float* kb = g_k + (size_t)bh * M_ * D_;
    const float* vb = g_v + (size_t)bh * M_ * D_;

    // ---- load Q tile, transpose into Qt (swizzled), pre-scale by SCALE ----
    {
        const int mg = tid >> 4, dg = tid & 15;
        const int r0 = mg << 2, d4 = dg << 2;
        const float* qp = qb + (size_t)(n0 + r0) * D_ + d4;
        float4 v0 = *(const float4*)(qp);
        float4 v1 = *(const float4*)(qp + D_);
        float4 v2 = *(const float4*)(qp + 2 * D_);
        float4 v3 = *(const float4*)(qp + 3 * D_);
        *(float4*)&Qt[SWZ(d4 + 0, mg)] = make_float4(v0.x * SCALE_, v1.x * SCALE_, v2.x * SCALE_, v3.x * SCALE_);
        *(float4*)&Qt[SWZ(d4 + 1, mg)] = make_float4(v0.y * SCALE_, v1.y * SCALE_, v2.y * SCALE_, v3.y * SCALE_);
        *(float4*)&Qt[SWZ(d4 + 2, mg)] = make_float4(v0.z * SCALE_, v1.z * SCALE_, v2.z * SCALE_, v3.z * SCALE_);
        *(float4*)&Qt[SWZ(d4 + 3, mg)] = make_float4(v0.w * SCALE_, v1.w * SCALE_, v2.w * SCALE_, v3.w * SCALE_);
    }

    float o[4][4];
    float mrow[4], lrow[4];
    #pragma unroll
    for (int i = 0; i < 4; ++i) {
        mrow[i] = -1e30f; lrow[i] = 0.f;
        #pragma unroll
        for (int j = 0; j < 4; ++j) o[i][j] = 0.f;
    }

    for (int t = 0; t < M_ / 64; ++t) {
        const int m0 = t * 64;

        // ---- load K tile (transposed, swizzled) + V tile (natural) ----
        {
            const int mg = tid >> 4, dg = tid & 15;
            const int r0 = mg << 2, d4 = dg << 2;
            const float* kp = kb + (size_t)(m0 + r0) * D_ + d4;
            float4 v0 = *(const float4*)(kp);
            float4 v1 = *(const float4*)(kp + D_);
            float4 v2 = *(const float4*)(kp + 2 * D_);
            float4 v3 = *(const float4*)(kp + 3 * D_);
            *(float4*)&KtP[SWZ(d4 + 0, mg)] = make_float4(v0.x, v1.x, v2.x, v3.x);
            *(float4*)&KtP[SWZ(d4 + 1, mg)] = make_float4(v0.y, v1.y, v2.y, v3.y);
            *(float4*)&KtP[SWZ(d4 + 2, mg)] = make_float4(v0.z, v1.z, v2.z, v3.z);
            *(float4*)&KtP[SWZ(d4 + 3, mg)] = make_float4(v0.w, v1.w, v2.w, v3.w);
            #pragma unroll
            for (int i = 0; i < 4; ++i) {
                int idx = (tid << 2) + (i << 10);
                int mm = idx >> 6, dd = idx & 63;
                *(float4*)&Vs[(mm << 6) + dd] =
                    *(const float4*)&vb[(size_t)(m0 + mm) * D_ + dd];
            }
        }
        __syncthreads();

        // ---- S = (Q*SCALE) K^T ----
        float s[4][4];
        #pragma unroll
        for (int i = 0; i < 4; ++i)
            #pragma unroll
            for (int j = 0; j < 4; ++j) s[i][j] = 0.f;

        #pragma unroll 8
        for (int k = 0; k < 64; ++k) {
            float4 qf = *(const float4*)&Qt[SWZ(k, ty)];
            float4 kf = *(const float4*)&KtP[SWZ(k, tx)];
            float a[4] = {qf.x, qf.y, qf.z, qf.w};
            float b[4] = {kf.x, kf.y, kf.z, kf.w};
            #pragma unroll
            for (int i = 0; i < 4; ++i)
                #pragma unroll
                for (int j = 0; j < 4; ++j)
                    s[i][j] = fmaf(a[i], b[j], s[i][j]);
        }

        // ---- online softmax (rows spread over the 16 tx lanes) ----
        #pragma unroll
        for (int i = 0; i < 4; ++i) {
            float mt = fmaxf(fmaxf(s[i][0], s[i][1]), fmaxf(s[i][2], s[i][3]));
            mt = fmaxf(mt, __shfl_xor_sync(0xffffffffu, mt, 8));
            mt = fmaxf(mt, __shfl_xor_sync(0xffffffffu, mt, 4));
            mt = fmaxf(mt, __shfl_xor_sync(0xffffffffu, mt, 2));
            mt = fmaxf(mt, __shfl_xor_sync(0xffffffffu, mt, 1));
            float mn = fmaxf(mrow[i], mt);
            float alpha = __expf(mrow[i] - mn);
            mrow[i] = mn;
            float rs = 0.f;
            #pragma unroll
            for (int j = 0; j < 4; ++j) {
                s[i][j] = __expf(s[i][j] - mn);
                rs += s[i][j];
            }
            rs += __shfl_xor_sync(0xffffffffu, rs, 8);
            rs += __shfl_xor_sync(0xffffffffu, rs, 4);
            rs += __shfl_xor_sync(0xffffffffu, rs, 2);
            rs += __shfl_xor_sync(0xffffffffu, rs, 1);
            lrow[i] = lrow[i] * alpha + rs;
            #pragma unroll
            for (int j = 0; j < 4; ++j) o[i][j] *= alpha;
        }
        __syncthreads();   // everyone done reading KtP as K

        // ---- store P^T into KtP (swizzled float4 stores) ----
        #pragma unroll
        for (int j = 0; j < 4; ++j)
            *(float4*)&KtP[SWZ((tx << 2) + j, ty)] =
                make_float4(s[0][j], s[1][j], s[2][j], s[3][j]);
        __syncthreads();

        // ---- O += P V ----
        #pragma unroll 8
        for (int m = 0; m < 64; ++m) {
            float4 pf = *(const float4*)&KtP[SWZ(m, ty)];
            float4 vf = *(const float4*)&Vs[(m << 6) + (tx << 2)];
            float p4[4] = {pf.x, pf.y, pf.z, pf.w};
            float v4[4] = {vf.x, vf.y, vf.z, vf.w};
            #pragma unroll
            for (int i = 0; i < 4; ++i)
                #pragma unroll
                for (int j = 0; j < 4; ++j)
                    o[i][j] = fmaf(p4[i], v4[j], o[i][j]);
        }
        __syncthreads();   // before next tile overwrites KtP / Vs
    }

    // ---- normalize + write (B,N,C) ----
    const int b = bh >> 4, h = bh & 15;
    #pragma unroll
    for (int i = 0; i < 4; ++i) {
        float inv = 1.0f / lrow[i];
        int n = n0 + (ty << 2) + i;
        float4 r = make_float4(o[i][0] * inv, o[i][1] * inv,
                               o[i][2] * inv, o[i][3] * inv);
        *(float4*)&g_x[((size_t)(b * N_ + n) * C_) + (h << 6) + (tx << 2)] = r;
    }
}

// ---------------------------------------------------------------------------
extern "C" void kernel_launch(void* const* d_in, const int* in_sizes, int n_in,
                              void* d_out, int out_size) {
    const float* query = (const float*)d_in[0];
    const float* key   = (const float*)d_in[1];
    const float* value = (const float*)d_in[2];
    const float* Wq    = (const float*)d_in[3];
    const float* Wk    = (const float*)d_in[4];
    const float* Wv    = (const float*)d_in[5];
    const float* Wp    = (const float*)d_in[6];
    const float* bp    = (const float*)d_in[7];
    float* out = (float*)d_out;

    dim3 gqkv(C_ / 128, (B_ * N_) / 128, 3);
    proj_qkv_kernel<<<gqkv, 256>>>(query, key, value, Wq, Wk, Wv);

    dim3 gfl(N_ / 64, B_ * H_);
    flash_kernel<<<gfl, 256>>>();

    dim3 gout(C_ / 128, (B_ * N_) / 128);
    proj_out_kernel<<<gout, 256>>>(Wp, bp, out);
}

// round 2
// speedup vs baseline: 3.1337x; 3.1337x over previous
#include <cuda_runtime.h>
#include <cstdint>

#define B_ 4
#define N_ 2048
#define M_ 2048
#define C_ 1024
#define H_ 16
#define D_ 64
#define SCALE_ 0.125f

// Scratch (allocation-free rule: __device__ globals)
__device__ float g_q[(size_t)B_ * H_ * N_ * D_];   // (B,H,N,D)
__device__ float g_k[(size_t)B_ * H_ * M_ * D_];   // (B,H,M,D)
__device__ float g_v[(size_t)B_ * H_ * M_ * D_];   // (B,H,M,D)
__device__ float g_x[(size_t)B_ * N_ * C_];        // (B,N,C) attention output

// ---------------------------------------------------------------------------
// tf32 helpers
// ---------------------------------------------------------------------------
__device__ __forceinline__ uint32_t f2tf(float x) {
    uint32_t u;
    asm("cvt.rna.tf32.f32 %0, %1;" : "=r"(u) : "f"(x));
    return u;
}

__device__ __forceinline__ void mma8(float c[4],
                                     uint32_t a0, uint32_t a1, uint32_t a2, uint32_t a3,
                                     uint32_t b0, uint32_t b1) {
    asm volatile(
        "mma.sync.aligned.m16n8k8.row.col.f32.tf32.tf32.f32 "
        "{%0,%1,%2,%3},{%4,%5,%6,%7},{%8,%9},{%0,%1,%2,%3};"
        : "+f"(c[0]), "+f"(c[1]), "+f"(c[2]), "+f"(c[3])
        : "r"(a0), "r"(a1), "r"(a2), "r"(a3), "r"(b0), "r"(b1));
}

// ---------------------------------------------------------------------------
// 128x128 tf32 GEMM tile (NT): out[r][c] = sum_k X[r][k] * W[c][k]
// 256 threads / 8 warps (4m x 2n). Warp tile 32x64. BK=32.
// smem stride 36 (== 4 mod 8): fragment scalar LDS conflict-free,
// uint4 tf32 stores conflict-free per 8-lane phase.
// ---------------------------------------------------------------------------
__device__ __forceinline__ void gemm_tile(const float* __restrict__ X,
                                          const float* __restrict__ W,
                                          int row0, int col0, float c[2][8][4]) {
    __shared__ uint32_t As[128 * 36];
    __shared__ uint32_t Bs[128 * 36];
    const int tid  = threadIdx.x;
    const int lane = tid & 31;
    const int g    = lane >> 2, tg = lane & 3;
    const int wid  = tid >> 5;
    const int wm   = (wid & 3) * 32;
    const int wn   = (wid >> 2) * 64;

    const float4* Xg = (const float4*)X;
    const float4* Wg = (const float4*)W;

    int rA[4], c4[4];
    float4 pa[4], pb[4];
    #pragma unroll
    for (int i = 0; i < 4; ++i) {
        int idx = tid + i * 256;
        rA[i] = idx >> 3;
        c4[i] = idx & 7;
        pa[i] = Xg[(size_t)(row0 + rA[i]) * (C_ / 4) + c4[i]];
        pb[i] = Wg[(size_t)(col0 + rA[i]) * (C_ / 4) + c4[i]];
    }

    for (int kt = 0; kt < C_ / 32; ++kt) {
        #pragma unroll
        for (int i = 0; i < 4; ++i) {
            *(uint4*)&As[rA[i] * 36 + c4[i] * 4] =
                make_uint4(f2tf(pa[i].x), f2tf(pa[i].y), f2tf(pa[i].z), f2tf(pa[i].w));
            *(uint4*)&Bs[rA[i] * 36 + c4[i] * 4] =
                make_uint4(f2tf(pb[i].x), f2tf(pb[i].y), f2tf(pb[i].z), f2tf(pb[i].w));
        }
        __syncthreads();
        if (kt + 1 < C_ / 32) {
            #pragma unroll
            for (int i = 0; i < 4; ++i) {
                pa[i] = Xg[(size_t)(row0 + rA[i]) * (C_ / 4) + (kt + 1) * 8 + c4[i]];
                pb[i] = Wg[(size_t)(col0 + rA[i]) * (C_ / 4) + (kt + 1) * 8 + c4[i]];
            }
        }
        #pragma unroll
        for (int kk = 0; kk < 4; ++kk) {
            uint32_t a[2][4];
            #pragma unroll
            for (int mt = 0; mt < 2; ++mt) {
                int ab = (wm + mt * 16 + g) * 36 + kk * 8 + tg;
                a[mt][0] = As[ab];
                a[mt][1] = As[ab + 8 * 36];
                a[mt][2] = As[ab + 4];
                a[mt][3] = As[ab + 8 * 36 + 4];
            }
            uint32_t b[8][2];
            #pragma unroll
            for (int nt = 0; nt < 8; ++nt) {
                int bb = (wn + nt * 8 + g) * 36 + kk * 8 + tg;
                b[nt][0] = Bs[bb];
                b[nt][1] = Bs[bb + 4];
            }
            #pragma unroll
            for (int mt = 0; mt < 2; ++mt)
                #pragma unroll
                for (int nt = 0; nt < 8; ++nt)
                    mma8(c[mt][nt], a[mt][0], a[mt][1], a[mt][2], a[mt][3],
                         b[nt][0], b[nt][1]);
        }
        __syncthreads();
    }
}

// ---------------------------------------------------------------------------
// QKV projections (z = 0/1/2 -> q/k/v), output scattered to (B,H,S,D)
// ---------------------------------------------------------------------------
__global__ void __launch_bounds__(256, 1) proj_qkv_kernel(
    const float* __restrict__ q_in, const float* __restrict__ k_in,
    const float* __restrict__ v_in, const float* __restrict__ Wq,
    const float* __restrict__ Wk, const float* __restrict__ Wv) {
    const float* X; const float* W; float* O;
    if (blockIdx.z == 0)      { X = q_in; W = Wq; O = g_q; }
    else if (blockIdx.z == 1) { X = k_in; W = Wk; O = g_k; }
    else                      { X = v_in; W = Wv; O = g_v; }

    const int row0 = blockIdx.y * 128;
    const int col0 = blockIdx.x * 128;

    float c[2][8][4];
    #pragma unroll
    for (int mt = 0; mt < 2; ++mt)
        #pragma unroll
        for (int nt = 0; nt < 8; ++nt)
            #pragma unroll
            for (int j = 0; j < 4; ++j) c[mt][nt][j] = 0.f;

    gemm_tile(X, W, row0, col0, c);

    const int lane = threadIdx.x & 31, wid = threadIdx.x >> 5;
    const int g = lane >> 2, tg = lane & 3;
    const int wm = (wid & 3) * 32, wn = (wid >> 2) * 64;

    #pragma unroll
    for (int mt = 0; mt < 2; ++mt)
        #pragma unroll
        for (int half = 0; half < 2; ++half) {
            int r = row0 + wm + mt * 16 + g + half * 8;
            int b = r >> 11, s = r & 2047;
            #pragma unroll
            for (int nt = 0; nt < 8; ++nt) {
                int col = col0 + wn + nt * 8 + 2 * tg;
                int h = col >> 6, d0 = col & 63;
                *(float2*)&O[((size_t)(b * H_ + h) * N_ + s) * D_ + d0] =
                    make_float2(c[mt][nt][half * 2], c[mt][nt][half * 2 + 1]);
            }
        }
}

// ---------------------------------------------------------------------------
// Output projection + bias -> d_out (B,N,C)
// ---------------------------------------------------------------------------
__global__ void __launch_bounds__(256, 1) proj_out_kernel(
    const float* __restrict__ Wp, const float* __restrict__ bp,
    float* __restrict__ out) {
    const int row0 = blockIdx.y * 128;
    const int col0 = blockIdx.x * 128;

    float c[2][8][4];
    #pragma unroll
    for (int mt = 0; mt < 2; ++mt)
        #pragma unroll
        for (int nt = 0; nt < 8; ++nt)
            #pragma unroll
            for (int j = 0; j < 4; ++j) c[mt][nt][j] = 0.f;

    gemm_tile(g_x, Wp, row0, col0, c);

    const int lane = threadIdx.x & 31, wid = threadIdx.x >> 5;
    const int g = lane >> 2, tg = lane & 3;
    const int wm = (wid & 3) * 32, wn = (wid >> 2) * 64;

    #pragma unroll
    for (int mt = 0; mt < 2; ++mt)
        #pragma unroll
        for (int half = 0; half < 2; ++half) {
            int r = row0 + wm + mt * 16 + g + half * 8;
            #pragma unroll
            for (int nt = 0; nt < 8; ++nt) {
                int col = col0 + wn + nt * 8 + 2 * tg;
                float2 bias = *(const float2*)&bp[col];
                *(float2*)&out[(size_t)r * C_ + col] =
                    make_float2(c[mt][nt][half * 2] + bias.x,
                                c[mt][nt][half * 2 + 1] + bias.y);
            }
        }
}

// ---------------------------------------------------------------------------
// Flash attention with tf32 mma.
// 128 threads / 4 warps; block = 64 query rows of one (b,h); key tile = 32.
// Warp w owns query rows w*16..w*16+15 (one m16 slab).
// smem:
//   Qs [64][68]  Q (pre-scaled, tf32)           17408 B
//   KP           K tile [32][68] / P tile [64][36]  9216 B (reused)
//   Vs [32][72]  V natural [key][d] (tf32)          9216 B
// All fragment LDS patterns verified conflict-free (stride == 4 mod 8 / 72).
// ---------------------------------------------------------------------------
__global__ void __launch_bounds__(128, 4) flash_kernel() {
    __shared__ uint32_t Qs[64 * 68];
    __shared__ uint32_t KP[64 * 36];   // max(32*68, 64*36) = 2304 words
    __shared__ uint32_t Vs[32 * 72];

    const int tid  = threadIdx.x;
    const int lane = tid & 31, w = tid >> 5;
    const int g    = lane >> 2, tg = lane & 3;
    const int bh   = blockIdx.y;
    const int n0   = blockIdx.x * 64;

    const float4* qb = (const float4*)(g_q + (size_t)bh * N_ * D_);
    const float4* kb = (const float4*)(g_k + (size_t)bh * M_ * D_);
    const float4* vb = (const float4*)(g_v + (size_t)bh * M_ * D_);

    // ---- load Q tile (pre-scaled by SCALE, tf32) ----
    #pragma unroll
    for (int i = 0; i < 8; ++i) {
        int idx = tid + i * 128;
        int r = idx >> 4, c4 = idx & 15;
        float4 v = qb[(size_t)(n0 + r) * 16 + c4];
        *(uint4*)&Qs[r * 68 + c4 * 4] =
            make_uint4(f2tf(v.x * SCALE_), f2tf(v.y * SCALE_),
                       f2tf(v.z * SCALE_), f2tf(v.w * SCALE_));
    }

    float o[8][4];
    float mrow[2], lrow[2];
    #pragma unroll
    for (int nt = 0; nt < 8; ++nt)
        #pragma unroll
        for (int j = 0; j < 4; ++j) o[nt][j] = 0.f;
    mrow[0] = mrow[1] = -1e30f;
    lrow[0] = lrow[1] = 0.f;

    // prefetch tile 0 K,V into registers
    int rKV[4], cKV[4];
    float4 pk[4], pv[4];
    #pragma unroll
    for (int i = 0; i < 4; ++i) {
        int idx = tid + i * 128;
        rKV[i] = idx >> 4;
        cKV[i] = idx & 15;
        pk[i] = kb[(size_t)rKV[i] * 16 + cKV[i]];
        pv[i] = vb[(size_t)rKV[i] * 16 + cKV[i]];
    }

    for (int t = 0; t < M_ / 32; ++t) {
        // ---- store K tile [32][68] + V tile [32][72] (tf32) ----
        #pragma unroll
        for (int i = 0; i < 4; ++i) {
            *(uint4*)&KP[rKV[i] * 68 + cKV[i] * 4] =
                make_uint4(f2tf(pk[i].x), f2tf(pk[i].y), f2tf(pk[i].z), f2tf(pk[i].w));
            *(uint4*)&Vs[rKV[i] * 72 + cKV[i] * 4] =
                make_uint4(f2tf(pv[i].x), f2tf(pv[i].y), f2tf(pv[i].z), f2tf(pv[i].w));
        }
        __syncthreads();
        if (t + 1 < M_ / 32) {
            #pragma unroll
            for (int i = 0; i < 4; ++i) {
                pk[i] = kb[(size_t)((t + 1) * 32 + rKV[i]) * 16 + cKV[i]];
                pv[i] = vb[(size_t)((t + 1) * 32 + rKV[i]) * 16 + cKV[i]];
            }
        }

        // ---- S = (Q*SCALE) K^T : m16 x n32 x k64 ----
        float s[4][4];
        #pragma unroll
        for (int nt = 0; nt < 4; ++nt)
            #pragma unroll
            for (int j = 0; j < 4; ++j) s[nt][j] = 0.f;

        #pragma unroll
        for (int kk = 0; kk < 8; ++kk) {
            int ab = (w * 16 + g) * 68 + kk * 8 + tg;
            uint32_t a0 = Qs[ab], a1 = Qs[ab + 8 * 68];
            uint32_t a2 = Qs[ab + 4], a3 = Qs[ab + 8 * 68 + 4];
            #pragma unroll
            for (int nt = 0; nt < 4; ++nt) {
                int bb = (nt * 8 + g) * 68 + kk * 8 + tg;
                mma8(s[nt], a0, a1, a2, a3, KP[bb], KP[bb + 4]);
            }
        }

        // ---- online softmax (reduction over the 4 tig lanes) ----
        #pragma unroll
        for (int r = 0; r < 2; ++r) {
            float mt_ = s[0][2 * r];
            #pragma unroll
            for (int nt = 0; nt < 4; ++nt) {
                mt_ = fmaxf(mt_, s[nt][2 * r]);
                mt_ = fmaxf(mt_, s[nt][2 * r + 1]);
            }
            mt_ = fmaxf(mt_, __shfl_xor_sync(0xffffffffu, mt_, 1));
            mt_ = fmaxf(mt_, __shfl_xor_sync(0xffffffffu, mt_, 2));
            float mn = fmaxf(mrow[r], mt_);
            float alpha = __expf(mrow[r] - mn);
            mrow[r] = mn;
            float rs = 0.f;
            #pragma unroll
            for (int nt = 0; nt < 4; ++nt) {
                s[nt][2 * r]     = __expf(s[nt][2 * r] - mn);
                s[nt][2 * r + 1] = __expf(s[nt][2 * r + 1] - mn);
                rs += s[nt][2 * r] + s[nt][2 * r + 1];
            }
            rs += __shfl_xor_sync(0xffffffffu, rs, 1);
            rs += __shfl_xor_sync(0xffffffffu, rs, 2);
            lrow[r] = lrow[r] * alpha + rs;
            #pragma unroll
            for (int nt = 0; nt < 8; ++nt) {
                o[nt][2 * r]     *= alpha;
                o[nt][2 * r + 1] *= alpha;
            }
        }
        __syncthreads();   // all warps done reading KP as K

        // ---- store P tile [64][36] (tf32) into KP ----
        #pragma unroll
        for (int r = 0; r < 2; ++r) {
            int prow = w * 16 + g + 8 * r;
            #pragma unroll
            for (int nt = 0; nt < 4; ++nt)
                *(uint2*)&KP[prow * 36 + nt * 8 + 2 * tg] =
                    make_uint2(f2tf(s[nt][2 * r]), f2tf(s[nt][2 * r + 1]));
        }
        __syncthreads();

        // ---- O += P V : m16 x n64 x k32 ----
        #pragma unroll
        for (int kk = 0; kk < 4; ++kk) {
            int ab = (w * 16 + g) * 36 + kk * 8 + tg;
            uint32_t a0 = KP[ab], a1 = KP[ab + 8 * 36];
            uint32_t a2 = KP[ab + 4], a3 = KP[ab + 8 * 36 + 4];
            #pragma unroll
            for (int nt = 0; nt < 8; ++nt) {
                uint32_t b0 = Vs[(kk * 8 + tg) * 72 + nt * 8 + g];
                uint32_t b1 = Vs[(kk * 8 + tg + 4) * 72 + nt * 8 + g];
                mma8(o[nt], a0, a1, a2, a3, b0, b1);
            }
        }
        __syncthreads();   // before next tile overwrites KP / Vs
    }

    // ---- normalize + write (B,N,C) ----
    const int b = bh >> 4, h = bh & 15;
    #pragma unroll
    for (int r = 0; r < 2; ++r) {
        float inv = 1.0f / lrow[r];
        int qrow = n0 + w * 16 + g + 8 * r;
        #pragma unroll
        for (int nt = 0; nt < 8; ++nt) {
            *(float2*)&g_x[(size_t)(b * N_ + qrow) * C_ + h * 64 + nt * 8 + 2 * tg] =
                make_float2(o[nt][2 * r] * inv, o[nt][2 * r + 1] * inv);
        }
    }
}

// ---------------------------------------------------------------------------
extern "C" void kernel_launch(void* const* d_in, const int* in_sizes, int n_in,
                              void* d_out, int out_size) {
    const float* query = (const float*)d_in[0];
    const float* key   = (const float*)d_in[1];
    const float* value = (const float*)d_in[2];
    const float* Wq    = (const float*)d_in[3];
    const float* Wk    = (const float*)d_in[4];
    const float* Wv    = (const float*)d_in[5];
    const float* Wp    = (const float*)d_in[6];
    const float* bp    = (const float*)d_in[7];
    float* out = (float*)d_out;

    dim3 gqkv(C_ / 128, (B_ * N_) / 128, 3);
    proj_qkv_kernel<<<gqkv, 256>>>(query, key, value, Wq, Wk, Wv);

    dim3 gfl(N_ / 64, B_ * H_);
    flash_kernel<<<gfl, 128>>>();

    dim3 gout(C_ / 128, (B_ * N_) / 128);
    proj_out_kernel<<<gout, 256>>>(Wp, bp, out);
}